// round 17
// baseline (speedup 1.0000x reference)
#include <cuda_runtime.h>
#include <cuda_bf16.h>
#include <cuda_fp16.h>
#include <stdint.h>

// Problem constants
#define NB   32
#define NC   64
#define NN   1024
#define NHEADS 4
#define ND   16

typedef unsigned long long ull;

// ---------------- scratch (device globals) ----------------
__device__ float g_q[NB * NC * NN];
__device__ float g_k[NB * NC * NN];
__device__ float g_v[NB * NC * NN];
__device__ float g_att[NB * NC * NN];
__device__ float g_chatt[NB * NC];
__device__ float g_sp[NB * NN];
__device__ float g_lnpart[NB * NHEADS * 2];   // per-(b,head) LN partial (s, ss)

// ---------------- f32x2 helpers ----------------
__device__ __forceinline__ ull fma2(ull a, ull b, ull c) {
    ull d;
    asm("fma.rn.f32x2 %0, %1, %2, %3;" : "=l"(d) : "l"(a), "l"(b), "l"(c));
    return d;
}
__device__ __forceinline__ ull pack2(float lo, float hi) {
    ull r;
    asm("mov.b64 %0, {%1, %2};" : "=l"(r) : "f"(lo), "f"(hi));
    return r;
}
__device__ __forceinline__ float2 unpack2(ull v) {
    float2 r;
    asm("mov.b64 {%0, %1}, %2;" : "=f"(r.x), "=f"(r.y) : "l"(v));
    return r;
}
// MUFU exp2 (fp32 — accuracy-validated path)
__device__ __forceinline__ float ex2(float x) {
    float r;
    asm("ex2.approx.ftz.f32 %0, %1;" : "=f"(r) : "f"(x));
    return r;
}
// fp16x2 pack (hi -> upper, lo -> lower)
__device__ __forceinline__ uint32_t hpack(float hi, float lo) {
    uint32_t r;
    asm("cvt.rn.f16x2.f32 %0, %1, %2;" : "=r"(r) : "f"(hi), "f"(lo));
    return r;
}
// saturating pack for P
__device__ __forceinline__ uint32_t hpacks(float hi, float lo) {
    uint32_t r;
    asm("cvt.rn.satfinite.f16x2.f32 %0, %1, %2;" : "=r"(r) : "f"(hi), "f"(lo));
    return r;
}
__device__ __forceinline__ float2 h22f2(uint32_t v) {
    __half2 h = *reinterpret_cast<__half2*>(&v);
    return __half22float2(h);
}

#define ONES_H2 0x3C003C00u   // fp16x2 (1.0, 1.0)

// =====================================================================
// K1: QKV projection (validated)
// =====================================================================
__global__ void __launch_bounds__(512, 1)
qkv_kernel(const float* __restrict__ x,
           const float* __restrict__ Wq, const float* __restrict__ bq,
           const float* __restrict__ Wk, const float* __restrict__ bk,
           const float* __restrict__ Wv, const float* __restrict__ bv)
{
    extern __shared__ float sm1[];
    float* xs = sm1;
    float* ws = sm1 + 64 * 256;

    const int b  = blockIdx.x >> 2;
    const int n0 = (blockIdx.x & 3) << 8;
    const int tid = threadIdx.x;

    const float* xb = x + b * (NC * NN);
    for (int idx = tid; idx < 64 * 256; idx += 512) {
        int c = idx >> 8, nl = idx & 255;
        xs[idx] = xb[c * NN + n0 + nl];
    }
    {
        const float* wsrc[3] = {Wq, Wk, Wv};
        for (int m = 0; m < 3; m++) {
            const float* w = wsrc[m];
            for (int idx = tid; idx < 4096; idx += 512) {
                int o = idx >> 6, c = idx & 63;
                ws[m * 4224 + c * 66 + o] = w[idx];
            }
        }
    }
    __syncthreads();

    const int nl = (tid & 127) << 1;
    const int og = (tid >> 7) << 4;

    ull acc[3][8][2];
    {
        const float* bias[3] = {bq, bk, bv};
#pragma unroll
        for (int m = 0; m < 3; m++)
#pragma unroll
            for (int p = 0; p < 8; p++) {
                ull bb = pack2(bias[m][og + 2 * p], bias[m][og + 2 * p + 1]);
                acc[m][p][0] = bb;
                acc[m][p][1] = bb;
            }
    }

#pragma unroll 4
    for (int c = 0; c < 64; c++) {
        float xv0 = xs[c * 256 + nl];
        float xv1 = xs[c * 256 + nl + 1];
        ull x0 = pack2(xv0, xv0);
        ull x1 = pack2(xv1, xv1);
#pragma unroll
        for (int m = 0; m < 3; m++) {
            const ull* wrow = (const ull*)&ws[m * 4224 + c * 66 + og];
#pragma unroll
            for (int p = 0; p < 8; p++) {
                ull w2 = wrow[p];
                acc[m][p][0] = fma2(x0, w2, acc[m][p][0]);
                acc[m][p][1] = fma2(x1, w2, acc[m][p][1]);
            }
        }
    }

    {
        float* dsts[3] = {g_q, g_k, g_v};
#pragma unroll
        for (int m = 0; m < 3; m++) {
            float* dst = dsts[m] + b * (NC * NN);
#pragma unroll
            for (int p = 0; p < 8; p++) {
                float2 a0 = unpack2(acc[m][p][0]);
                float2 a1 = unpack2(acc[m][p][1]);
                int o = og + 2 * p;
                *(float2*)&dst[o * NN + n0 + nl]       = make_float2(a0.x, a1.x);
                *(float2*)&dst[(o + 1) * NN + n0 + nl] = make_float2(a0.y, a1.y);
            }
        }
    }
}

// =====================================================================
// fp16 mma.sync helpers
// =====================================================================
__device__ __forceinline__ void mmaS16(float& d0, float& d1, float& d2, float& d3,
    uint32_t a0, uint32_t a1, uint32_t a2, uint32_t a3,
    uint32_t b0, uint32_t b1, float c01, float c23)
{
    asm("mma.sync.aligned.m16n8k16.row.col.f32.f16.f16.f32 "
        "{%0,%1,%2,%3}, {%4,%5,%6,%7}, {%8,%9}, {%10,%10,%11,%11};"
        : "=f"(d0), "=f"(d1), "=f"(d2), "=f"(d3)
        : "r"(a0), "r"(a1), "r"(a2), "r"(a3), "r"(b0), "r"(b1),
          "f"(c01), "f"(c23));
}
// k16 PV: A = P fragments from two j8 halves, B = V pair (or ones)
__device__ __forceinline__ void mmaPV16(float* O,
    uint32_t a0, uint32_t a1, uint32_t a2, uint32_t a3,
    uint32_t b0, uint32_t b1)
{
    asm("mma.sync.aligned.m16n8k16.row.col.f32.f16.f16.f32 "
        "{%0,%1,%2,%3}, {%4,%5,%6,%7}, {%8,%9}, {%0,%1,%2,%3};"
        : "+f"(O[0]), "+f"(O[1]), "+f"(O[2]), "+f"(O[3])
        : "r"(a0), "r"(a1), "r"(a2), "r"(a3), "r"(b0), "r"(b1));
}

// smem layout (bytes)
#define SM2_K    0            // K fp16: 1024 rows x 32B, XOR16 swizzle  (32768)
#define SM2_V    32768        // V fp16: 16 rows x 2064B                 (33024)
#define SM2_CH   65792        // ch table fp16: 32 rows x 2064B          (66048)
#define SM2_CW   131840       // cw table fp16: 32 rows x 2064B          (66048)
#define SM2_RH   197888       // rel_h staged fp32 / partial maxes / LN reduce
#define SM2_RW   199936       // rel_w staged fp32 / row maxes MM[64]
#define SM2_TOT  201984

// =====================================================================
// K2: flash attention. fp32 score math + fp32 MUFU exp; P fp16 satfinite;
// PV and l as k16 MMAs over j16 blocks; LN partials fused.
// =====================================================================
__global__ void __launch_bounds__(512, 1)
attn_fa_kernel(const float* __restrict__ rel_h, const float* __restrict__ rel_w)
{
    extern __shared__ char sm[];
    const int tid  = threadIdx.x;
    const int warp = tid >> 5;
    const int lane = tid & 31;
    const int g = lane >> 2;
    const int t = lane & 3;
    const int b  = blockIdx.x >> 2;
    const int hh = blockIdx.x & 3;

    const float* qb = g_q + b * (NC * NN) + hh * (ND * NN);
    const float* kb = g_k + b * (NC * NN) + hh * (ND * NN);
    const float* vb = g_v + b * (NC * NN) + hh * (ND * NN);
    const float L2E = 1.4426950408889634f;

    float* RH = (float*)(sm + SM2_RH);
    float* RW = (float*)(sm + SM2_RW);

    // ---- stage rel (x L2E): 512 threads = 16 d x 32 pos ----
    {
        int d = tid >> 5, ip = tid & 31;
        RH[tid] = rel_h[(hh * ND + d) * 32 + ip] * L2E;
        RW[tid] = rel_w[(hh * ND + d) * 32 + ip] * L2E;
    }

    // ---- fill K fp16 (swizzled) ----
#pragma unroll
    for (int rep = 0; rep < 2; rep++) {
        const int j = tid + (rep << 9);
        char* base = sm + SM2_K + j * 32;
        const uint32_t xo = (uint32_t)((j & 4) << 2);
#pragma unroll
        for (int p = 0; p < 8; p++) {
            uint32_t v = hpack(kb[(2 * p + 1) * NN + j], kb[2 * p * NN + j]);
            *(uint32_t*)(base + ((uint32_t)(4 * p) ^ xo)) = v;
        }
    }
    // ---- fill V fp16 ----
    {
        const int jp = tid << 1;
#pragma unroll
        for (int d = 0; d < 16; d++) {
            *(uint32_t*)(sm + SM2_V + d * 2064 + tid * 4) =
                hpack(vb[d * NN + jp + 1], vb[d * NN + jp]);
        }
    }
    __syncthreads();   // #1

    // ---- compute ch/cw tables (fp16), f32x2-packed over ih pairs ----
#pragma unroll
    for (int rep = 0; rep < 2; rep++) {
        const int j = tid + (rep << 9);
        ull q2[16];
#pragma unroll
        for (int d = 0; d < 16; d++) {
            float qv = qb[d * NN + j];
            q2[d] = pack2(qv, qv);
        }
        for (int ihp = 0; ihp < 16; ihp++) {
            ull sh2 = 0ULL, sw2 = 0ULL;
#pragma unroll
            for (int d = 0; d < 16; d++) {
                sh2 = fma2(q2[d], *(const ull*)&RH[d * 32 + 2 * ihp], sh2);
                sw2 = fma2(q2[d], *(const ull*)&RW[d * 32 + 2 * ihp], sw2);
            }
            float2 sh = unpack2(sh2);
            float2 sw = unpack2(sw2);
            *(__half*)(sm + SM2_CH + (2 * ihp) * 2064 + 2 * j)     = __float2half_rn(sh.x);
            *(__half*)(sm + SM2_CH + (2 * ihp + 1) * 2064 + 2 * j) = __float2half_rn(sh.y);
            *(__half*)(sm + SM2_CW + (2 * ihp) * 2064 + 2 * j)     = __float2half_rn(sw.x);
            *(__half*)(sm + SM2_CW + (2 * ihp + 1) * 2064 + 2 * j) = __float2half_rn(sw.y);
        }
    }
    __syncthreads();   // #2

    // ---- row maxima of tables (overflow guard) ----
    {
        const int row = tid >> 3, seg = tid & 7;
        const char* tb = (row < 32) ? (sm + SM2_CH + row * 2064)
                                    : (sm + SM2_CW + (row - 32) * 2064);
        const uint32_t* p32 = (const uint32_t*)(tb + seg * 256);
        float mx = -1e30f;
#pragma unroll 8
        for (int jj = 0; jj < 64; jj++) {
            float2 v = h22f2(p32[jj]);
            mx = fmaxf(mx, fmaxf(v.x, v.y));
        }
        RH[tid] = mx;
    }
    __syncthreads();   // #3
    float* MM = RW;
    if (tid < 64) {
        const float* pm = RH + tid * 8;
        float m = pm[0];
#pragma unroll
        for (int s2 = 1; s2 < 8; s2++) m = fmaxf(m, pm[s2]);
        MM[tid] = m;
    }
    __syncthreads();   // #4

    // ---- build A fragments + row biases ----
    const int i0 = warp << 6;
    uint32_t fa[4][4];
    float nbA[4], nbB[4];
#pragma unroll
    for (int mt = 0; mt < 4; mt++) {
        const int r0 = i0 + (mt << 4) + g;
        const int r1 = r0 + 8;
#pragma unroll
        for (int half = 0; half < 2; half++) {
            const int dA = 2 * t + half * 8;
            fa[mt][half * 2 + 0] = hpack(qb[(dA + 1) * NN + r0] * L2E,
                                         qb[dA * NN + r0] * L2E);
            fa[mt][half * 2 + 1] = hpack(qb[(dA + 1) * NN + r1] * L2E,
                                         qb[dA * NN + r1] * L2E);
        }
        const int ihA = ((mt & 1) << 4) + g;
        const int iw  = 2 * warp + (mt >> 1);
        const float mw = MM[32 + iw];
        nbA[mt] = -(MM[ihA] + mw + 2.0f);
        nbB[mt] = -(MM[ihA + 8] + mw + 2.0f);
    }

    // ---- mainloop: j16 blocks, PV as k16 ----
    float O[4][2][4];
    float L[4][4];
#pragma unroll
    for (int mt = 0; mt < 4; mt++) {
#pragma unroll
        for (int dn = 0; dn < 2; dn++)
#pragma unroll
            for (int r = 0; r < 4; r++) O[mt][dn][r] = 0.f;
#pragma unroll
        for (int r = 0; r < 4; r++) L[mt][r] = 0.f;
    }

    const uint32_t koff0 = ((uint32_t)(4 * t))      ^ (uint32_t)((g & 4) << 2);
    const uint32_t koff1 = ((uint32_t)(16 + 4 * t)) ^ (uint32_t)((g & 4) << 2);
    const char* kbase  = sm + SM2_K + g * 32;
    const char* vbase0 = sm + SM2_V + g * 2064 + t * 4;
    const char* vbase1 = sm + SM2_V + (8 + g) * 2064 + t * 4;
    const char* chb0 = sm + SM2_CH + g * 2064 + t * 4;          // mt even, r0
    const char* chb1 = sm + SM2_CH + (g + 8) * 2064 + t * 4;    // mt even, r1
    const char* chb2 = sm + SM2_CH + (16 + g) * 2064 + t * 4;   // mt odd, r0
    const char* chb3 = sm + SM2_CH + (24 + g) * 2064 + t * 4;   // mt odd, r1
    const char* cwb0 = sm + SM2_CW + (2 * warp) * 2064 + t * 4;       // mt 0,1
    const char* cwb1 = sm + SM2_CW + (2 * warp + 1) * 2064 + t * 4;   // mt 2,3

    for (int j16 = 0; j16 < 64; j16++) {
        uint32_t Pa[4][2], Pb[4][2];
        uint32_t vb0a, vb1a, vb0b, vb1b;
#pragma unroll
        for (int hB = 0; hB < 2; hB++) {
            const int j8 = 2 * j16 + hB;
            const uint32_t jb32 = (uint32_t)j8 << 8;
            const uint32_t jb2  = (uint32_t)j8 << 4;
            const uint32_t kb0 = *(const uint32_t*)(kbase + jb32 + koff0);
            const uint32_t kb1 = *(const uint32_t*)(kbase + jb32 + koff1);
            if (hB == 0) {
                vb0a = *(const uint32_t*)(vbase0 + jb2);
                vb1a = *(const uint32_t*)(vbase1 + jb2);
            } else {
                vb0b = *(const uint32_t*)(vbase0 + jb2);
                vb1b = *(const uint32_t*)(vbase1 + jb2);
            }
            const float2 cw0 = h22f2(*(const uint32_t*)(cwb0 + jb2));
            const float2 cw1 = h22f2(*(const uint32_t*)(cwb1 + jb2));
            const float2 ch0 = h22f2(*(const uint32_t*)(chb0 + jb2));
            const float2 ch1 = h22f2(*(const uint32_t*)(chb1 + jb2));
            const float2 ch2 = h22f2(*(const uint32_t*)(chb2 + jb2));
            const float2 ch3 = h22f2(*(const uint32_t*)(chb3 + jb2));

#pragma unroll
            for (int mt = 0; mt < 4; mt++) {
                const float2 cA = (mt & 1) ? ch2 : ch0;
                const float2 cB = (mt & 1) ? ch3 : ch1;
                const float2 cw = (mt & 2) ? cw1 : cw0;
                float d0, d1, d2, d3;
                mmaS16(d0, d1, d2, d3, fa[mt][0], fa[mt][1], fa[mt][2], fa[mt][3],
                       kb0, kb1, nbA[mt], nbB[mt]);
                float p0 = ex2(d0 + cA.x + cw.x);
                float p1 = ex2(d1 + cA.y + cw.y);
                float p2 = ex2(d2 + cB.x + cw.x);
                float p3 = ex2(d3 + cB.y + cw.y);
                uint32_t P0 = hpacks(p1, p0);
                uint32_t P1 = hpacks(p3, p2);
                if (hB == 0) { Pa[mt][0] = P0; Pa[mt][1] = P1; }
                else         { Pb[mt][0] = P0; Pb[mt][1] = P1; }
            }
        }
        // PV + l as k16 MMAs (A = {Pa_r0, Pa_r1, Pb_r0, Pb_r1})
#pragma unroll
        for (int mt = 0; mt < 4; mt++) {
            mmaPV16(O[mt][0], Pa[mt][0], Pa[mt][1], Pb[mt][0], Pb[mt][1], vb0a, vb0b);
            mmaPV16(O[mt][1], Pa[mt][0], Pa[mt][1], Pb[mt][0], Pb[mt][1], vb1a, vb1b);
            mmaPV16(L[mt],    Pa[mt][0], Pa[mt][1], Pb[mt][0], Pb[mt][1], ONES_H2, ONES_H2);
        }
    }

    // ---- epilogue: O/l + fused LN partial stats ----
    float* ob = g_att + b * (NC * NN) + hh * (ND * NN);
    float s_ln = 0.f, ss_ln = 0.f;
#pragma unroll
    for (int mt = 0; mt < 4; mt++) {
        const float inv0 = 1.f / L[mt][0];
        const float inv1 = 1.f / L[mt][2];
        const int r0 = i0 + (mt << 4) + g;
        const int r1 = r0 + 8;
#pragma unroll
        for (int dn = 0; dn < 2; dn++) {
            const int c0 = dn * 8 + 2 * t;
            float v00 = O[mt][dn][0] * inv0;
            float v01 = O[mt][dn][1] * inv0;
            float v10 = O[mt][dn][2] * inv1;
            float v11 = O[mt][dn][3] * inv1;
            ob[c0 * NN + r0]       = v00;
            ob[(c0 + 1) * NN + r0] = v01;
            ob[c0 * NN + r1]       = v10;
            ob[(c0 + 1) * NN + r1] = v11;
            s_ln  += v00 + v01 + v10 + v11;
            ss_ln += v00 * v00 + v01 * v01 + v10 * v10 + v11 * v11;
        }
    }
#pragma unroll
    for (int off = 16; off > 0; off >>= 1) {
        s_ln  += __shfl_xor_sync(0xffffffffu, s_ln, off);
        ss_ln += __shfl_xor_sync(0xffffffffu, ss_ln, off);
    }
    __syncthreads();
    if (lane == 0) { RH[warp * 2] = s_ln; RH[warp * 2 + 1] = ss_ln; }
    __syncthreads();
    if (tid == 0) {
        float s = 0.f, ss = 0.f;
#pragma unroll
        for (int w2 = 0; w2 < 16; w2++) { s += RH[w2 * 2]; ss += RH[w2 * 2 + 1]; }
        g_lnpart[blockIdx.x * 2]     = s;
        g_lnpart[blockIdx.x * 2 + 1] = ss;
    }
}

// =====================================================================
// K3: x channel stats + CBAM MLP
// =====================================================================
__global__ void __launch_bounds__(256)
stats_kernel(const float* __restrict__ x,
             const float* __restrict__ ca_w1, const float* __restrict__ ca_b1,
             const float* __restrict__ ca_w2, const float* __restrict__ ca_b2)
{
    const int b = blockIdx.x, tid = threadIdx.x;
    __shared__ float r1[256], r2[256];
    __shared__ float savg[64], smx2[64], hid[8];

    {
        int c = tid >> 2, qq = tid & 3;
        const float* xc = x + b * (NC * NN) + c * NN + qq * 256;
        float sa = 0.f, mx = -3.4e38f;
        for (int t2 = 0; t2 < 256; t2++) {
            float v = xc[t2];
            sa += v;
            mx = fmaxf(mx, v);
        }
        r1[tid] = sa; r2[tid] = mx;
    }
    __syncthreads();
    if (tid < 64) {
        float av = 0.f, m = -3.4e38f;
        for (int q2 = 0; q2 < 4; q2++) {
            av += r1[tid * 4 + q2];
            m = fmaxf(m, r2[tid * 4 + q2]);
        }
        savg[tid] = av * (1.f / 1024.f);
        smx2[tid] = m;
    }
    __syncthreads();
    if (tid < 8) {
        int r = tid & 3;
        const float* src = (tid < 4) ? savg : smx2;
        float h = ca_b1[r];
        for (int c2 = 0; c2 < 64; c2++) h += ca_w1[r * 64 + c2] * src[c2];
        hid[tid] = fmaxf(h, 0.f);
    }
    __syncthreads();
    if (tid < 64) {
        float o = 2.f * ca_b2[tid];
        for (int r = 0; r < 4; r++) o += ca_w2[tid * 4 + r] * (hid[r] + hid[4 + r]);
        g_chatt[b * NC + tid] = 1.f / (1.f + __expf(-o));
    }
}

// =====================================================================
// K4a: CBAM spatial map — 4 CTAs per batch
// =====================================================================
__global__ void __launch_bounds__(1024)
spatial_kernel(const float* __restrict__ x,
               const float* __restrict__ sa_w, const float* __restrict__ sa_b)
{
    const int b = blockIdx.x >> 2, qd = blockIdx.x & 3, tid = threadIdx.x;
    __shared__ float fm[NN], fx[NN], chs[64], wsh[98];
    if (tid < 64) chs[tid] = g_chatt[b * NC + tid];
    if (tid < 98) wsh[tid] = sa_w[tid];
    __syncthreads();

    {
        const float* xb = x + b * (NC * NN) + tid;
        float s = 0.f, m = -3.4e38f;
#pragma unroll
        for (int c = 0; c < 64; c++) {
            float v = chs[c] * xb[c * NN];
            s += v;
            m = fmaxf(m, v);
        }
        fm[tid] = s * (1.f / 64.f);
        fx[tid] = m;
    }
    __syncthreads();

    if (tid < 256) {
        const int iw = (qd << 3) + (tid >> 5), ih = tid & 31;
        float o = sa_b[0];
#pragma unroll
        for (int ky = 0; ky < 7; ky++) {
            int y = iw + ky - 3;
            if ((unsigned)y < 32u) {
#pragma unroll
                for (int kx = 0; kx < 7; kx++) {
                    int xx2 = ih + kx - 3;
                    if ((unsigned)xx2 < 32u) {
                        int fi = y * 32 + xx2;
                        o += wsh[ky * 7 + kx] * fm[fi] + wsh[49 + ky * 7 + kx] * fx[fi];
                    }
                }
            }
        }
        g_sp[b * NN + iw * 32 + ih] = 1.f / (1.f + __expf(-o));
    }
}

// =====================================================================
// K4b: final fuse — float4 vectorized; LN from per-head partials
// =====================================================================
__global__ void __launch_bounds__(256)
final_kernel(const float* __restrict__ x,
             const float* __restrict__ ln_g, const float* __restrict__ ln_b,
             float* __restrict__ out)
{
    int i4 = blockIdx.x * 256 + threadIdx.x;     // 0 .. 524287
    int base = i4 << 2;
    int b  = base >> 16;
    int cn = base & 65535;
    int c  = cn >> 10;
    int n  = cn & 1023;

    float s = 0.f, ss = 0.f;
#pragma unroll
    for (int h = 0; h < 4; h++) {
        s  += g_lnpart[(b * 4 + h) * 2];
        ss += g_lnpart[(b * 4 + h) * 2 + 1];
    }
    float mu   = s * (1.f / 65536.f);
    float var  = ss * (1.f / 65536.f) - mu * mu;
    float rstd = rsqrtf(var + 1e-5f);

    float4 xv = *(const float4*)&x[base];
    float4 av = *(const float4*)&g_att[base];
    float4 gg = *(const float4*)&ln_g[cn];
    float4 bb = *(const float4*)&ln_b[cn];
    float4 sp = *(const float4*)&g_sp[b * NN + n];
    float ca  = g_chatt[b * NC + c];

    float4 o;
    o.x = (av.x - mu) * rstd * gg.x + bb.x + 2.f * xv.x + sp.x * ca * xv.x;
    o.y = (av.y - mu) * rstd * gg.y + bb.y + 2.f * xv.y + sp.y * ca * xv.y;
    o.z = (av.z - mu) * rstd * gg.z + bb.z + 2.f * xv.z + sp.z * ca * xv.z;
    o.w = (av.w - mu) * rstd * gg.w + bb.w + 2.f * xv.w + sp.w * ca * xv.w;
    *(float4*)&out[base] = o;
}

// =====================================================================
extern "C" void kernel_launch(void* const* d_in, const int* in_sizes, int n_in,
                              void* d_out, int out_size)
{
    const float* x     = (const float*)d_in[0];
    const float* Wq    = (const float*)d_in[1];
    const float* bq    = (const float*)d_in[2];
    const float* Wk    = (const float*)d_in[3];
    const float* bk    = (const float*)d_in[4];
    const float* Wv    = (const float*)d_in[5];
    const float* bv    = (const float*)d_in[6];
    const float* rel_h = (const float*)d_in[7];
    const float* rel_w = (const float*)d_in[8];
    const float* ln_g  = (const float*)d_in[9];
    const float* ln_b  = (const float*)d_in[10];
    const float* ca_w1 = (const float*)d_in[11];
    const float* ca_b1 = (const float*)d_in[12];
    const float* ca_w2 = (const float*)d_in[13];
    const float* ca_b2 = (const float*)d_in[14];
    const float* sa_w  = (const float*)d_in[15];
    const float* sa_b  = (const float*)d_in[16];
    float* out = (float*)d_out;

    const int smem1 = (64 * 256 + 3 * 64 * 66) * (int)sizeof(float);
    cudaFuncSetAttribute(qkv_kernel,     cudaFuncAttributeMaxDynamicSharedMemorySize, smem1);
    cudaFuncSetAttribute(attn_fa_kernel, cudaFuncAttributeMaxDynamicSharedMemorySize, SM2_TOT);

    qkv_kernel<<<NB * 4, 512, smem1>>>(x, Wq, bq, Wk, bk, Wv, bv);
    attn_fa_kernel<<<NB * NHEADS, 512, SM2_TOT>>>(rel_h, rel_w);
    stats_kernel<<<NB, 256>>>(x, ca_w1, ca_b1, ca_w2, ca_b2);
    spatial_kernel<<<NB * 4, 1024>>>(x, sa_w, sa_b);
    final_kernel<<<(NB * NC * NN) / 1024, 256>>>(x, ln_g, ln_b, out);
}